// round 2
// baseline (speedup 1.0000x reference)
#include <cuda_runtime.h>
#include <cuda_fp16.h>
#include <cstdint>

// Problem constants
namespace {
constexpr int S_    = 2048;
constexpr int H_    = 32;
constexpr int G_    = 4;     // GQA group
constexpr int D_    = 128;
constexpr int QSTR  = 4096;  // H*D floats per token row (q, out)
constexpr int KSTR  = 1024;  // HKV*D floats per token row (k, v)
constexpr int BM    = 64;    // q rows per CTA
constexpr int BN    = 64;    // kv rows per tile
constexpr int STRIDE = 136;  // smem row stride in halves (128 + 8 pad)
}

__device__ __forceinline__ uint32_t smem_addr(const void* p) {
    return (uint32_t)__cvta_generic_to_shared(p);
}

__device__ __forceinline__ void ldm_x4(uint32_t& r0, uint32_t& r1, uint32_t& r2, uint32_t& r3, uint32_t a) {
    asm volatile("ldmatrix.sync.aligned.m8n8.x4.shared.b16 {%0,%1,%2,%3}, [%4];\n"
        : "=r"(r0), "=r"(r1), "=r"(r2), "=r"(r3) : "r"(a));
}
__device__ __forceinline__ void ldm_x4_t(uint32_t& r0, uint32_t& r1, uint32_t& r2, uint32_t& r3, uint32_t a) {
    asm volatile("ldmatrix.sync.aligned.m8n8.x4.trans.shared.b16 {%0,%1,%2,%3}, [%4];\n"
        : "=r"(r0), "=r"(r1), "=r"(r2), "=r"(r3) : "r"(a));
}
__device__ __forceinline__ void mma16816(float* c, const uint32_t* a, uint32_t b0, uint32_t b1) {
    asm volatile("mma.sync.aligned.m16n8k16.row.col.f32.f16.f16.f32 "
        "{%0,%1,%2,%3}, {%4,%5,%6,%7}, {%8,%9}, {%0,%1,%2,%3};\n"
        : "+f"(c[0]), "+f"(c[1]), "+f"(c[2]), "+f"(c[3])
        : "r"(a[0]), "r"(a[1]), "r"(a[2]), "r"(a[3]), "r"(b0), "r"(b1));
}
__device__ __forceinline__ uint32_t packh2(float x, float y) {
    half2 h = __floats2half2_rn(x, y);
    return *reinterpret_cast<uint32_t*>(&h);
}

__global__ __launch_bounds__(128, 1)
void fa2_kernel(const float* __restrict__ q,
                const float* __restrict__ k,
                const float* __restrict__ v,
                float* __restrict__ o)
{
    __shared__ __align__(16) half sK[BM * STRIDE];  // also used to stage Q
    __shared__ __align__(16) half sV[BN * STRIDE];

    const int tid  = threadIdx.x;
    const int warp = tid >> 5;
    const int lane = tid & 31;
    const int qt   = blockIdx.x;       // q tile within sequence
    const int hq   = blockIdx.y;       // flat query head (hkv*G + g)
    const int b    = blockIdx.z;
    const int hkv  = hq / G_;
    const int qbase = qt * BM;

    const size_t tok0 = (size_t)b * S_ + qbase;
    const float* qg = q + tok0 * QSTR + (size_t)hq * D_;
    const float* kg = k + (size_t)b * S_ * KSTR + (size_t)hkv * D_;
    const float* vg = v + (size_t)b * S_ * KSTR + (size_t)hkv * D_;

    // ---- Stage Q tile (fp32 -> fp16) into sK ----
    for (int i = tid; i < BM * 32; i += 128) {
        int r = i >> 5, c = (i & 31) * 4;
        float4 f = *(const float4*)(qg + (size_t)r * QSTR + c);
        half2* d = (half2*)(sK + r * STRIDE + c);
        d[0] = __floats2half2_rn(f.x, f.y);
        d[1] = __floats2half2_rn(f.z, f.w);
    }
    __syncthreads();

    // ---- Q fragments: 8 k16-chunks, persistent in registers ----
    uint32_t qf[8][4];
    {
        int j = lane >> 3, m = lane & 7;
        int row = warp * 16 + ((j & 1) ? 8 : 0) + m;   // tiles: r0-7/k0, r8-15/k0, r0-7/k8, r8-15/k8
        int col = (j >= 2) ? 8 : 0;
        #pragma unroll
        for (int kc = 0; kc < 8; kc++) {
            uint32_t a = smem_addr(sK + row * STRIDE + kc * 16 + col);
            ldm_x4(qf[kc][0], qf[kc][1], qf[kc][2], qf[kc][3], a);
        }
    }

    // ---- Online-softmax state (log2 domain, scale folded in) ----
    constexpr float SL = 0.08838834764831845f * 1.4426950408889634f;  // SCALE * log2(e)
    float ot[16][4];
    #pragma unroll
    for (int t = 0; t < 16; t++)
        #pragma unroll
        for (int i = 0; i < 4; i++) ot[t][i] = 0.f;
    float m0 = -1e30f, m1 = -1e30f, l0 = 0.f, l1 = 0.f;

    const int r0g = qbase + warp * 16 + (lane >> 2);  // global q row (within seq) for c0/c1
    const int r1g = r0g + 8;                          // for c2/c3
    const int ntile = qt + 1;

    for (int j = 0; j < ntile; j++) {
        __syncthreads();  // previous iteration done with sK/sV
        // ---- Load K and V tiles (fp32 -> fp16) ----
        const float* kt = kg + (size_t)(j * BN) * KSTR;
        const float* vt = vg + (size_t)(j * BN) * KSTR;
        for (int i = tid; i < BN * 32; i += 128) {
            int r = i >> 5, c = (i & 31) * 4;
            float4 fk = *(const float4*)(kt + (size_t)r * KSTR + c);
            half2* dk = (half2*)(sK + r * STRIDE + c);
            dk[0] = __floats2half2_rn(fk.x, fk.y);
            dk[1] = __floats2half2_rn(fk.z, fk.w);
            float4 fv = *(const float4*)(vt + (size_t)r * KSTR + c);
            half2* dv = (half2*)(sV + r * STRIDE + c);
            dv[0] = __floats2half2_rn(fv.x, fv.y);
            dv[1] = __floats2half2_rn(fv.z, fv.w);
        }
        __syncthreads();

        // ---- S = Q K^T (16 x 64 per warp) ----
        float sc[8][4];
        #pragma unroll
        for (int t = 0; t < 8; t++)
            #pragma unroll
            for (int i = 0; i < 4; i++) sc[t][i] = 0.f;
        {
            int jj = lane >> 3, mm = lane & 7;
            int rn = ((jj >= 2) ? 8 : 0) + mm;        // K row (n) within 16-group
            int ck = (jj & 1) ? 8 : 0;                // k-offset within chunk
            #pragma unroll
            for (int kc = 0; kc < 8; kc++) {
                #pragma unroll
                for (int np = 0; np < 4; np++) {
                    uint32_t a = smem_addr(sK + (np * 16 + rn) * STRIDE + kc * 16 + ck);
                    uint32_t b0, b1, b2, b3;
                    ldm_x4(b0, b1, b2, b3, a);
                    mma16816(sc[2 * np],     qf[kc], b0, b1);
                    mma16816(sc[2 * np + 1], qf[kc], b2, b3);
                }
            }
        }

        // ---- scale (+ causal mask on diagonal tile) ----
        if (j == ntile - 1) {
            int c0 = j * BN + (lane & 3) * 2;
            #pragma unroll
            for (int nt = 0; nt < 8; nt++) {
                int cc = c0 + nt * 8;
                sc[nt][0] = (cc     <= r0g) ? sc[nt][0] * SL : -1e30f;
                sc[nt][1] = (cc + 1 <= r0g) ? sc[nt][1] * SL : -1e30f;
                sc[nt][2] = (cc     <= r1g) ? sc[nt][2] * SL : -1e30f;
                sc[nt][3] = (cc + 1 <= r1g) ? sc[nt][3] * SL : -1e30f;
            }
        } else {
            #pragma unroll
            for (int nt = 0; nt < 8; nt++)
                #pragma unroll
                for (int i = 0; i < 4; i++) sc[nt][i] *= SL;
        }

        // ---- online softmax ----
        float nm0 = m0, nm1 = m1;
        #pragma unroll
        for (int nt = 0; nt < 8; nt++) {
            nm0 = fmaxf(nm0, fmaxf(sc[nt][0], sc[nt][1]));
            nm1 = fmaxf(nm1, fmaxf(sc[nt][2], sc[nt][3]));
        }
        nm0 = fmaxf(nm0, __shfl_xor_sync(0xffffffffu, nm0, 1));
        nm0 = fmaxf(nm0, __shfl_xor_sync(0xffffffffu, nm0, 2));
        nm1 = fmaxf(nm1, __shfl_xor_sync(0xffffffffu, nm1, 1));
        nm1 = fmaxf(nm1, __shfl_xor_sync(0xffffffffu, nm1, 2));
        float a0 = exp2f(m0 - nm0), a1 = exp2f(m1 - nm1);
        m0 = nm0; m1 = nm1;

        float rs0 = 0.f, rs1 = 0.f;
        #pragma unroll
        for (int nt = 0; nt < 8; nt++) {
            sc[nt][0] = exp2f(sc[nt][0] - m0);
            sc[nt][1] = exp2f(sc[nt][1] - m0);
            sc[nt][2] = exp2f(sc[nt][2] - m1);
            sc[nt][3] = exp2f(sc[nt][3] - m1);
            rs0 += sc[nt][0] + sc[nt][1];
            rs1 += sc[nt][2] + sc[nt][3];
        }
        rs0 += __shfl_xor_sync(0xffffffffu, rs0, 1);
        rs0 += __shfl_xor_sync(0xffffffffu, rs0, 2);
        rs1 += __shfl_xor_sync(0xffffffffu, rs1, 1);
        rs1 += __shfl_xor_sync(0xffffffffu, rs1, 2);
        l0 = l0 * a0 + rs0;
        l1 = l1 * a1 + rs1;
        #pragma unroll
        for (int t = 0; t < 16; t++) {
            ot[t][0] *= a0; ot[t][1] *= a0;
            ot[t][2] *= a1; ot[t][3] *= a1;
        }

        // ---- O += P V ----
        {
            int jj = lane >> 3, mm = lane & 7;
            int rk = (jj & 1) * 8 + mm;               // V row (kv) within 16-group
            int cn = (jj >= 2) ? 8 : 0;               // d-offset within 16-group
            #pragma unroll
            for (int kvc = 0; kvc < 4; kvc++) {
                uint32_t af[4];
                af[0] = packh2(sc[2 * kvc][0],     sc[2 * kvc][1]);
                af[1] = packh2(sc[2 * kvc][2],     sc[2 * kvc][3]);
                af[2] = packh2(sc[2 * kvc + 1][0], sc[2 * kvc + 1][1]);
                af[3] = packh2(sc[2 * kvc + 1][2], sc[2 * kvc + 1][3]);
                #pragma unroll
                for (int dp = 0; dp < 8; dp++) {
                    uint32_t b0, b1, b2, b3;
                    uint32_t a = smem_addr(sV + (kvc * 16 + rk) * STRIDE + dp * 16 + cn);
                    ldm_x4_t(b0, b1, b2, b3, a);
                    mma16816(ot[2 * dp],     af, b0, b1);
                    mma16816(ot[2 * dp + 1], af, b2, b3);
                }
            }
        }
    }

    // ---- Epilogue: normalize and store fp32 ----
    float inv0 = 1.f / l0, inv1 = 1.f / l1;
    float* og = o + tok0 * QSTR + (size_t)hq * D_;
    int rr0 = warp * 16 + (lane >> 2);
    #pragma unroll
    for (int nt = 0; nt < 16; nt++) {
        int c = nt * 8 + (lane & 3) * 2;
        float2 w0 = make_float2(ot[nt][0] * inv0, ot[nt][1] * inv0);
        float2 w1 = make_float2(ot[nt][2] * inv1, ot[nt][3] * inv1);
        *(float2*)(og + (size_t)rr0 * QSTR + c)       = w0;
        *(float2*)(og + (size_t)(rr0 + 8) * QSTR + c) = w1;
    }
}

extern "C" void kernel_launch(void* const* d_in, const int* in_sizes, int n_in,
                              void* d_out, int out_size)
{
    const float* q = (const float*)d_in[0];
    const float* k = (const float*)d_in[1];
    const float* v = (const float*)d_in[2];
    float* o = (float*)d_out;
    dim3 grid(S_ / BM, H_, 2);   // (q tiles, heads, batch)
    dim3 block(128);
    fa2_kernel<<<grid, block>>>(q, k, v, o);
}

// round 4
// speedup vs baseline: 1.3582x; 1.3582x over previous
#include <cuda_runtime.h>
#include <cuda_fp16.h>
#include <cstdint>

namespace {
constexpr int S_    = 2048;
constexpr int H_    = 32;
constexpr int G_    = 4;
constexpr int D_    = 128;
constexpr int QSTR  = 4096;   // H*D floats per token (q, out)
constexpr int KSTR  = 1024;   // HKV*D per token (k, v)
constexpr int BM    = 128;    // q rows per CTA
constexpr int BN    = 64;     // kv rows per tile
constexpr int NT    = 256;    // threads
constexpr int STRIDE = 136;   // smem row stride in halves (128 + 8 pad)
constexpr int KV_ELE = BN * STRIDE;       // halves per K (or V) buffer
constexpr int SMEM_BYTES = (BM * STRIDE + 4 * KV_ELE) * 2;  // sQ + 2*sK + 2*sV
}

// fp16 copies of K/V (scratch; __device__ globals are allowed)
__device__ __align__(16) half g_kh[2 * S_ * KSTR];
__device__ __align__(16) half g_vh[2 * S_ * KSTR];

__device__ __forceinline__ uint32_t smem_u32(const void* p) {
    return (uint32_t)__cvta_generic_to_shared(p);
}
__device__ __forceinline__ void cp_async16(uint32_t dst, const void* src) {
    asm volatile("cp.async.cg.shared.global [%0], [%1], 16;\n" :: "r"(dst), "l"(src));
}
__device__ __forceinline__ void ldm_x4(uint32_t& r0, uint32_t& r1, uint32_t& r2, uint32_t& r3, uint32_t a) {
    asm volatile("ldmatrix.sync.aligned.m8n8.x4.shared.b16 {%0,%1,%2,%3}, [%4];\n"
        : "=r"(r0), "=r"(r1), "=r"(r2), "=r"(r3) : "r"(a));
}
__device__ __forceinline__ void ldm_x4_t(uint32_t& r0, uint32_t& r1, uint32_t& r2, uint32_t& r3, uint32_t a) {
    asm volatile("ldmatrix.sync.aligned.m8n8.x4.trans.shared.b16 {%0,%1,%2,%3}, [%4];\n"
        : "=r"(r0), "=r"(r1), "=r"(r2), "=r"(r3) : "r"(a));
}
__device__ __forceinline__ void mma16816(float* c, const uint32_t* a, uint32_t b0, uint32_t b1) {
    asm volatile("mma.sync.aligned.m16n8k16.row.col.f32.f16.f16.f32 "
        "{%0,%1,%2,%3}, {%4,%5,%6,%7}, {%8,%9}, {%0,%1,%2,%3};\n"
        : "+f"(c[0]), "+f"(c[1]), "+f"(c[2]), "+f"(c[3])
        : "r"(a[0]), "r"(a[1]), "r"(a[2]), "r"(a[3]), "r"(b0), "r"(b1));
}
__device__ __forceinline__ uint32_t packh2(float x, float y) {
    half2 h = __floats2half2_rn(x, y);
    return *reinterpret_cast<uint32_t*>(&h);
}

// ---- K/V fp32 -> fp16 convert pass ----
__global__ void cvt_kernel(const float* __restrict__ k, const float* __restrict__ v) {
    const size_t n4 = (size_t)2 * S_ * KSTR / 4;   // float4 count per array
    for (size_t i = (size_t)blockIdx.x * blockDim.x + threadIdx.x;
         i < 2 * n4; i += (size_t)gridDim.x * blockDim.x) {
        bool isK = i < n4;
        size_t ii = isK ? i : i - n4;
        float4 f = isK ? ((const float4*)k)[ii] : ((const float4*)v)[ii];
        uint2 h;
        h.x = packh2(f.x, f.y);
        h.y = packh2(f.z, f.w);
        ((uint2*)(isK ? g_kh : g_vh))[ii] = h;
    }
}

__global__ __launch_bounds__(NT, 1)
void fa2_kernel(const float* __restrict__ q, float* __restrict__ o)
{
    extern __shared__ __align__(16) half smem[];
    half* sQ    = smem;                 // BM * STRIDE
    half* sKbuf = smem + BM * STRIDE;   // 2 * KV_ELE
    half* sVbuf = sKbuf + 2 * KV_ELE;   // 2 * KV_ELE

    const int tid  = threadIdx.x;
    const int warp = tid >> 5;
    const int lane = tid & 31;
    const int qt   = (int)gridDim.x - 1 - (int)blockIdx.x;  // heavy tiles first
    const int hq   = blockIdx.y;
    const int b    = blockIdx.z;
    const int hkv  = hq / G_;
    const int qbase = qt * BM;
    const int ntile = (qbase + BM) / BN;   // = 2*(qt+1)

    const size_t tok0 = (size_t)b * S_ + qbase;
    const half* kg = g_kh + ((size_t)b * S_) * KSTR + (size_t)hkv * D_;
    const half* vg = g_vh + ((size_t)b * S_) * KSTR + (size_t)hkv * D_;

    // ---- issue cp.async for KV tiles 0 and 1 (always exist: ntile >= 2) ----
    auto load_kv = [&](int j, int buf) {
        const half* kt = kg + (size_t)(j * BN) * KSTR;
        const half* vt = vg + (size_t)(j * BN) * KSTR;
        half* dK = sKbuf + buf * KV_ELE;
        half* dV = sVbuf + buf * KV_ELE;
        #pragma unroll
        for (int i = tid; i < BN * 16; i += NT) {      // 16 x 16B chunks per row
            int r = i >> 4, c = (i & 15) * 8;          // c in halves
            cp_async16(smem_u32(dK + r * STRIDE + c), kt + (size_t)r * KSTR + c);
            cp_async16(smem_u32(dV + r * STRIDE + c), vt + (size_t)r * KSTR + c);
        }
    };
    load_kv(0, 0);
    asm volatile("cp.async.commit_group;\n");
    load_kv(1, 1);
    asm volatile("cp.async.commit_group;\n");

    // ---- stage Q (fp32 -> fp16) while cp.async is in flight ----
    const float* qg = q + tok0 * QSTR + (size_t)hq * D_;
    for (int i = tid; i < BM * 32; i += NT) {
        int r = i >> 5, c = (i & 31) * 4;
        float4 f = *(const float4*)(qg + (size_t)r * QSTR + c);
        half2* d = (half2*)(sQ + r * STRIDE + c);
        d[0] = __floats2half2_rn(f.x, f.y);
        d[1] = __floats2half2_rn(f.z, f.w);
    }
    __syncthreads();

    // ---- Q fragments (persistent) ----
    uint32_t qf[8][4];
    {
        int j = lane >> 3, m = lane & 7;
        int row = warp * 16 + ((j & 1) ? 8 : 0) + m;
        int col = (j >= 2) ? 8 : 0;
        #pragma unroll
        for (int kc = 0; kc < 8; kc++) {
            uint32_t a = smem_u32(sQ + row * STRIDE + kc * 16 + col);
            ldm_x4(qf[kc][0], qf[kc][1], qf[kc][2], qf[kc][3], a);
        }
    }

    constexpr float SL = 0.08838834764831845f * 1.4426950408889634f;  // SCALE*log2(e)
    float ot[16][4];
    #pragma unroll
    for (int t = 0; t < 16; t++)
        #pragma unroll
        for (int i = 0; i < 4; i++) ot[t][i] = 0.f;
    float m0 = -1e30f, m1 = -1e30f, l0 = 0.f, l1 = 0.f;

    const int r0g = qbase + warp * 16 + (lane >> 2);
    const int r1g = r0g + 8;

    for (int j = 0; j < ntile; j++) {
        asm volatile("cp.async.wait_group 1;\n");
        __syncthreads();

        const half* sK = sKbuf + (j & 1) * KV_ELE;
        const half* sV = sVbuf + (j & 1) * KV_ELE;

        // fully-masked warp tiles contribute nothing: skip compute entirely
        bool skip = (qbase + warp * 16 + 15) < j * BN;
        if (!skip) {
            // ---- S = Q K^T ----
            float sc[8][4];
            #pragma unroll
            for (int t = 0; t < 8; t++)
                #pragma unroll
                for (int i = 0; i < 4; i++) sc[t][i] = 0.f;
            {
                int jj = lane >> 3, mm = lane & 7;
                int rn = ((jj >= 2) ? 8 : 0) + mm;
                int ck = (jj & 1) ? 8 : 0;
                #pragma unroll
                for (int kc = 0; kc < 8; kc++) {
                    #pragma unroll
                    for (int np = 0; np < 4; np++) {
                        uint32_t a = smem_u32(sK + (np * 16 + rn) * STRIDE + kc * 16 + ck);
                        uint32_t b0, b1, b2, b3;
                        ldm_x4(b0, b1, b2, b3, a);
                        mma16816(sc[2 * np],     qf[kc], b0, b1);
                        mma16816(sc[2 * np + 1], qf[kc], b2, b3);
                    }
                }
            }

            // ---- scale (+ causal mask if tile straddles the diagonal) ----
            bool needMask = (j * BN + BN - 1) > (qbase + warp * 16);
            if (needMask) {
                int c0 = j * BN + (lane & 3) * 2;
                #pragma unroll
                for (int nt = 0; nt < 8; nt++) {
                    int cc = c0 + nt * 8;
                    sc[nt][0] = (cc     <= r0g) ? sc[nt][0] * SL : -1e30f;
                    sc[nt][1] = (cc + 1 <= r0g) ? sc[nt][1] * SL : -1e30f;
                    sc[nt][2] = (cc     <= r1g) ? sc[nt][2] * SL : -1e30f;
                    sc[nt][3] = (cc + 1 <= r1g) ? sc[nt][3] * SL : -1e30f;
                }
            } else {
                #pragma unroll
                for (int nt = 0; nt < 8; nt++)
                    #pragma unroll
                    for (int i = 0; i < 4; i++) sc[nt][i] *= SL;
            }

            // ---- online softmax ----
            float nm0 = m0, nm1 = m1;
            #pragma unroll
            for (int nt = 0; nt < 8; nt++) {
                nm0 = fmaxf(nm0, fmaxf(sc[nt][0], sc[nt][1]));
                nm1 = fmaxf(nm1, fmaxf(sc[nt][2], sc[nt][3]));
            }
            nm0 = fmaxf(nm0, __shfl_xor_sync(0xffffffffu, nm0, 1));
            nm0 = fmaxf(nm0, __shfl_xor_sync(0xffffffffu, nm0, 2));
            nm1 = fmaxf(nm1, __shfl_xor_sync(0xffffffffu, nm1, 1));
            nm1 = fmaxf(nm1, __shfl_xor_sync(0xffffffffu, nm1, 2));
            float a0 = exp2f(m0 - nm0), a1 = exp2f(m1 - nm1);
            m0 = nm0; m1 = nm1;

            float rs0 = 0.f, rs1 = 0.f;
            #pragma unroll
            for (int nt = 0; nt < 8; nt++) {
                sc[nt][0] = exp2f(sc[nt][0] - m0);
                sc[nt][1] = exp2f(sc[nt][1] - m0);
                sc[nt][2] = exp2f(sc[nt][2] - m1);
                sc[nt][3] = exp2f(sc[nt][3] - m1);
                rs0 += sc[nt][0] + sc[nt][1];
                rs1 += sc[nt][2] + sc[nt][3];
            }
            rs0 += __shfl_xor_sync(0xffffffffu, rs0, 1);
            rs0 += __shfl_xor_sync(0xffffffffu, rs0, 2);
            rs1 += __shfl_xor_sync(0xffffffffu, rs1, 1);
            rs1 += __shfl_xor_sync(0xffffffffu, rs1, 2);
            l0 = l0 * a0 + rs0;
            l1 = l1 * a1 + rs1;
            #pragma unroll
            for (int t = 0; t < 16; t++) {
                ot[t][0] *= a0; ot[t][1] *= a0;
                ot[t][2] *= a1; ot[t][3] *= a1;
            }

            // ---- O += P V ----
            {
                int jj = lane >> 3, mm = lane & 7;
                int rk = (jj & 1) * 8 + mm;
                int cn = (jj >= 2) ? 8 : 0;
                #pragma unroll
                for (int kvc = 0; kvc < 4; kvc++) {
                    uint32_t af[4];
                    af[0] = packh2(sc[2 * kvc][0],     sc[2 * kvc][1]);
                    af[1] = packh2(sc[2 * kvc][2],     sc[2 * kvc][3]);
                    af[2] = packh2(sc[2 * kvc + 1][0], sc[2 * kvc + 1][1]);
                    af[3] = packh2(sc[2 * kvc + 1][2], sc[2 * kvc + 1][3]);
                    #pragma unroll
                    for (int dp = 0; dp < 8; dp++) {
                        uint32_t b0, b1, b2, b3;
                        uint32_t a = smem_u32(sV + (kvc * 16 + rk) * STRIDE + dp * 16 + cn);
                        ldm_x4_t(b0, b1, b2, b3, a);
                        mma16816(ot[2 * dp],     af, b0, b1);
                        mma16816(ot[2 * dp + 1], af, b2, b3);
                    }
                }
            }
        }

        __syncthreads();            // all warps done with buf (j&1)
        if (j + 2 < ntile) load_kv(j + 2, j & 1);
        asm volatile("cp.async.commit_group;\n");   // always commit (empty ok)
    }

    // ---- epilogue ----
    float inv0 = 1.f / l0, inv1 = 1.f / l1;
    float* og = o + tok0 * QSTR + (size_t)hq * D_;
    int rr0 = warp * 16 + (lane >> 2);
    #pragma unroll
    for (int nt = 0; nt < 16; nt++) {
        int c = nt * 8 + (lane & 3) * 2;
        float2 w0 = make_float2(ot[nt][0] * inv0, ot[nt][1] * inv0);
        float2 w1 = make_float2(ot[nt][2] * inv1, ot[nt][3] * inv1);
        *(float2*)(og + (size_t)rr0 * QSTR + c)       = w0;
        *(float2*)(og + (size_t)(rr0 + 8) * QSTR + c) = w1;
    }
}

extern "C" void kernel_launch(void* const* d_in, const int* in_sizes, int n_in,
                              void* d_out, int out_size)
{
    const float* q = (const float*)d_in[0];
    const float* k = (const float*)d_in[1];
    const float* v = (const float*)d_in[2];
    float* o = (float*)d_out;

    cvt_kernel<<<2048, 256>>>(k, v);

    static int configured = 0;
    cudaFuncSetAttribute(fa2_kernel, cudaFuncAttributeMaxDynamicSharedMemorySize, SMEM_BYTES);
    (void)configured;

    dim3 grid(S_ / BM, H_, 2);
    fa2_kernel<<<grid, NT, SMEM_BYTES>>>(q, o);
}